// round 16
// baseline (speedup 1.0000x reference)
#include <cuda_runtime.h>
#include <math.h>

// ---------------- scratch (static device globals; no allocation) ----------------
#define NVOX 4194304  // 2*64*32*32*32
#define XP_SEQ 2112   // 64-float LN-stats header + 2048 data
#define XP_TOTAL (2048 * XP_SEQ)
static __device__ float g_tmp[NVOX];
static __device__ float g_x1[NVOX];
static __device__ float g_xp0[XP_TOTAL];
static __device__ float g_xp1[XP_TOTAL];
static __device__ float g_xp2[XP_TOTAL];
static __device__ float g_o0[NVOX];
static __device__ float g_o1[NVOX];
static __device__ float g_o2[NVOX];
static __device__ float g_cwT[2 * 110592];   // conv weights [(ci*27+kk)*64 + co]
static __device__ float2 g_ipart[128];       // inorm2 stats (mu, rstd) per (b*64+c)

// transposed weights: left 8192 | right 8192 | delta 16384 | out' 8192 | bc 4096 |
// S2 64 | B2 64
#define WT_LEFT  0
#define WT_RIGHT 8192
#define WT_DELTA 16384
#define WT_OUT   32768
#define WT_BC    40960
#define WT_S2    45056
#define WT_B2    45120
#define WT_TOTAL 45184
static __device__ float g_wT[WT_TOTAL];

typedef unsigned long long u64t;

// ---------------- f32x2 packed-FMA helpers (Blackwell FFMA2, PTX-only) ----------
__device__ __forceinline__ u64t pk2(float lo, float hi) {
    u64t r; asm("mov.b64 %0, {%1,%2};" : "=l"(r) : "f"(lo), "f"(hi)); return r;
}
__device__ __forceinline__ void upk2(u64t v, float& lo, float& hi) {
    asm("mov.b64 {%0,%1}, %2;" : "=f"(lo), "=f"(hi) : "l"(v));
}
__device__ __forceinline__ u64t fma2(u64t a, u64t b, u64t c) {
    u64t d; asm("fma.rn.f32x2 %0, %1, %2, %3;" : "=l"(d) : "l"(a), "l"(b), "l"(c)); return d;
}

// ---------------- scalar helpers ----------------
__device__ __forceinline__ float softplus_f(float x) {
    return fmaxf(x, 0.f) + log1pf(__expf(-fabsf(x)));
}
__device__ __forceinline__ float silu_f(float x) {
    return x / (1.f + __expf(-x));
}
__device__ __forceinline__ float ex2_fast(float x) {   // MUFU pipe
    float r; asm("ex2.approx.ftz.f32 %0, %1;" : "=f"(r) : "f"(x)); return r;
}
__device__ __forceinline__ float lrelu_f(float a) {
    return a >= 0.f ? a : 0.01f * a;
}
__device__ __forceinline__ void cpa16(unsigned int dst, const void* src) {
    asm volatile("cp.async.cg.shared.global [%0], [%1], 16;" :: "r"(dst), "l"(src));
}

// ---------------- conv weight transpose: cw[co][ci][kk] -> [(ci*27+kk)*64+co] ----
__global__ void cwT_kernel(const float* __restrict__ cw1, const float* __restrict__ cw2,
                           float* __restrict__ gcw) {
    int i = blockIdx.x * 256 + threadIdx.x;   // 0 .. 221183
    if (i < 110592) {
        int co = i & 63, r = i >> 6;
        gcw[i] = cw1[co * 1728 + r];
    } else if (i < 221184) {
        int j = i - 110592;
        int co = j & 63, r = j >> 6;
        gcw[i] = cw2[co * 1728 + r];
    }
}

// =================================================================================
// conv3d 3x3x3, C=64->64, +bias. grid (32 h, 4 co-groups of 16, 2 b), block 256.
// cp.async double-buffered 2-ci slabs; ALL load addressing hoisted out of the
// slab loop (slab-invariant per-thread offsets in registers).
// =================================================================================
#define CONV_SMEM_BYTES ((2 * 8160 + 2 * 864) * 4)
__global__ void __launch_bounds__(256, 2) conv3d_kernel(
    const float* __restrict__ xin, const float* __restrict__ gcw,
    const float* __restrict__ cb, float* __restrict__ out)
{
    extern __shared__ float cs[];
    float* TIN = cs;                 // [2 buf][2 ci][3 kh][34 rows][40]
    float* WS  = cs + 16320;         // [2 buf][2 ci][27 kk][16 co]

    int tid = threadIdx.x;
    int lane = tid & 31, wid = tid >> 5;
    int h = blockIdx.x;
    int cog = blockIdx.y;            // co base = cog*16
    int b = blockIdx.z;

    unsigned int tin_u = (unsigned int)__cvta_generic_to_shared(TIN);
    unsigned int ws_u  = (unsigned int)__cvta_generic_to_shared(WS);

    for (int idx = tid; idx < 16320; idx += 256) TIN[idx] = 0.f;
    __syncthreads();

    // ---- slab-invariant per-thread load addressing ----
    unsigned int dsto[3];            // smem byte offset within a ci-tile
    unsigned int srco[3];            // gmem float offset within a channel plane
    bool vld[3];
#pragma unroll
    for (int r = 0; r < 3; r++) {
        int j = r * 256 + tid;
        int kh = j >> 8, qq = j & 255;
        int w = qq >> 3, seg = qq & 7;
        int hh = h + kh - 1;
        vld[r]  = (hh >= 0 && hh < 32);
        srco[r] = (unsigned int)(hh * 1024 + w * 32 + seg * 4);
        dsto[r] = (unsigned int)(kh * 1360 + (w + 1) * 40 + 4 + seg * 4) * 4u;
    }
    bool wldr = tid < 216;
    unsigned int wdst = 0, wsrc = 0, wci2 = 0;
    if (wldr) {
        int ci2 = tid / 108, r = tid % 108;
        int kk = r >> 2, qd = r & 3;
        wci2 = (unsigned int)ci2;
        wdst = (unsigned int)(ci2 * 432 + kk * 16 + qd * 4) * 4u;
        wsrc = (unsigned int)((kk * 16 + cog * 4 + qd) * 4);   // + ci*1728 at use
    }
    const float* xbase = xin + (size_t)(b * 64) * 32768;

    auto load_slab = [&](int s, int buf) {
#pragma unroll
        for (int ci2 = 0; ci2 < 2; ci2++) {
            const float* src_base = xbase + (size_t)(2 * s + ci2) * 32768;
            unsigned int dstb = tin_u + (unsigned int)(buf * 8160 + ci2 * 4080) * 4u;
#pragma unroll
            for (int r = 0; r < 3; r++)
                if (vld[r]) cpa16(dstb + dsto[r], src_base + srco[r]);
        }
        if (wldr) {
            unsigned int ci = 2 * s + wci2;
            cpa16(ws_u + (unsigned int)(buf * 864) * 4u + wdst, gcw + ci * 1728 + wsrc);
        }
        asm volatile("cp.async.commit_group;" ::: "memory");
    };

    u64t acc2[32];
#pragma unroll
    for (int i = 0; i < 32; i++) acc2[i] = 0ULL;

    load_slab(0, 0);
    asm volatile("cp.async.wait_group 0;" ::: "memory");
    __syncthreads();

    for (int s = 0; s < 32; s++) {
        int cur = s & 1;
        if (s < 31) load_slab(s + 1, cur ^ 1);    // async, overlaps compute
#pragma unroll
        for (int ci2 = 0; ci2 < 2; ci2++) {
            const float* tb = TIN + cur * 8160 + ci2 * 4080;
            const ulonglong2* wb = (const ulonglong2*)(WS + cur * 864 + ci2 * 432);
#pragma unroll
            for (int kh = 0; kh < 3; kh++) {
                const float* tkh = tb + kh * 1360;
#pragma unroll
                for (int kw = 0; kw < 3; kw++) {
#pragma unroll
                    for (int kd = 0; kd < 3; kd++) {
                        int kk = kh * 9 + kw * 3 + kd;
                        ulonglong2 wq0 = wb[kk * 4];
                        ulonglong2 wq1 = wb[kk * 4 + 1];
                        ulonglong2 wq2 = wb[kk * 4 + 2];
                        ulonglong2 wq3 = wb[kk * 4 + 3];
#pragma unroll
                        for (int ws = 0; ws < 4; ws++) {
                            float v = tkh[(ws * 8 + wid + kw) * 40 + 3 + lane + kd];
                            u64t vv = pk2(v, v);
                            acc2[ws * 8 + 0] = fma2(vv, wq0.x, acc2[ws * 8 + 0]);
                            acc2[ws * 8 + 1] = fma2(vv, wq0.y, acc2[ws * 8 + 1]);
                            acc2[ws * 8 + 2] = fma2(vv, wq1.x, acc2[ws * 8 + 2]);
                            acc2[ws * 8 + 3] = fma2(vv, wq1.y, acc2[ws * 8 + 3]);
                            acc2[ws * 8 + 4] = fma2(vv, wq2.x, acc2[ws * 8 + 4]);
                            acc2[ws * 8 + 5] = fma2(vv, wq2.y, acc2[ws * 8 + 5]);
                            acc2[ws * 8 + 6] = fma2(vv, wq3.x, acc2[ws * 8 + 6]);
                            acc2[ws * 8 + 7] = fma2(vv, wq3.y, acc2[ws * 8 + 7]);
                        }
                    }
                }
            }
        }
        asm volatile("cp.async.wait_group 0;" ::: "memory");
        __syncthreads();
    }

#pragma unroll
    for (int ws = 0; ws < 4; ws++) {
        int w = ws * 8 + wid;
        size_t o = ((size_t)(b * 64 + cog * 16)) * 32768 + (size_t)h * 1024 + w * 32 + lane;
#pragma unroll
        for (int p = 0; p < 8; p++) {
            float alo, ahi;
            upk2(acc2[ws * 8 + p], alo, ahi);
            out[o + (size_t)(p * 2) * 32768]     = alo + cb[cog * 16 + p * 2];
            out[o + (size_t)(p * 2 + 1) * 32768] = ahi + cb[cog * 16 + p * 2 + 1];
        }
    }
}

// ---------------- InstanceNorm3d + LeakyReLU(0.01) + residual (1024 thr) --------
__global__ void inorm_res_kernel(const float* __restrict__ y,
                                 const float* __restrict__ res,
                                 float* __restrict__ out) {
    int bc = blockIdx.x;
    const float4* yp = (const float4*)(y + (size_t)bc * 32768);
    int tid = threadIdx.x;
    int lane = tid & 31, wid = tid >> 5;
    float s1 = 0.f, s2 = 0.f;
    for (int i = tid; i < 8192; i += 1024) {
        float4 v = yp[i];
        s1 += v.x + v.y + v.z + v.w;
        s2 += v.x * v.x + v.y * v.y + v.z * v.z + v.w * v.w;
    }
#pragma unroll
    for (int o = 16; o > 0; o >>= 1) {
        s1 += __shfl_xor_sync(0xffffffffu, s1, o);
        s2 += __shfl_xor_sync(0xffffffffu, s2, o);
    }
    __shared__ float r1[32], r2[32];
    __shared__ float mu_s, rstd_s;
    if (lane == 0) { r1[wid] = s1; r2[wid] = s2; }
    __syncthreads();
    if (tid < 32) {
        float a = r1[tid], c = r2[tid];
#pragma unroll
        for (int o = 16; o > 0; o >>= 1) {
            a += __shfl_xor_sync(0xffffffffu, a, o);
            c += __shfl_xor_sync(0xffffffffu, c, o);
        }
        if (tid == 0) {
            float mu = a * (1.f / 32768.f);
            float var = c * (1.f / 32768.f) - mu * mu;
            mu_s = mu; rstd_s = rsqrtf(var + 1e-5f);
        }
    }
    __syncthreads();
    float mu = mu_s, rstd = rstd_s;
    const float4* rp = (const float4*)(res + (size_t)bc * 32768);
    float4* op = (float4*)(out + (size_t)bc * 32768);
    for (int i = tid; i < 8192; i += 1024) {
        float4 v = yp[i]; float4 r = rp[i]; float4 o;
        float a;
        a = (v.x - mu) * rstd; o.x = r.x + lrelu_f(a);
        a = (v.y - mu) * rstd; o.y = r.y + lrelu_f(a);
        a = (v.z - mu) * rstd; o.z = r.z + lrelu_f(a);
        a = (v.w - mu) * rstd; o.w = r.w + lrelu_f(a);
        op[i] = o;
    }
}

// ---------------- inorm2 stats only: (mu, rstd) per (b,c) ----------------------
__global__ void inorm_stats_kernel(const float* __restrict__ y, float2* __restrict__ part) {
    int bc = blockIdx.x;
    const float4* yp = (const float4*)(y + (size_t)bc * 32768);
    int tid = threadIdx.x;
    int lane = tid & 31, wid = tid >> 5;
    float s1 = 0.f, s2 = 0.f;
    for (int i = tid; i < 8192; i += 1024) {
        float4 v = yp[i];
        s1 += v.x + v.y + v.z + v.w;
        s2 += v.x * v.x + v.y * v.y + v.z * v.z + v.w * v.w;
    }
#pragma unroll
    for (int o = 16; o > 0; o >>= 1) {
        s1 += __shfl_xor_sync(0xffffffffu, s1, o);
        s2 += __shfl_xor_sync(0xffffffffu, s2, o);
    }
    __shared__ float r1[32], r2[32];
    if (lane == 0) { r1[wid] = s1; r2[wid] = s2; }
    __syncthreads();
    if (tid < 32) {
        float a = r1[tid], c = r2[tid];
#pragma unroll
        for (int o = 16; o > 0; o >>= 1) {
            a += __shfl_xor_sync(0xffffffffu, a, o);
            c += __shfl_xor_sync(0xffffffffu, c, o);
        }
        if (tid == 0) {
            float mu = a * (1.f / 32768.f);
            float var = c * (1.f / 32768.f) - mu * mu;
            part[bc] = make_float2(mu, rsqrtf(var + 1e-5f));
        }
    }
}

// =================================================================================
// trans: x2 computed INLINE from (tmp, x1, inorm2 stats); writes 3 axis copies
// [seq][64-hdr: mu32|rs32][t][c] with per-voxel LN stats. Also weight transposes.
// grid 2048 + 177, block 256.
// =================================================================================
__global__ void trans_kernel(const float* __restrict__ tmp2, const float* __restrict__ x1,
                             const float2* __restrict__ ipart,
                             const float* __restrict__ left_w, const float* __restrict__ right_w,
                             const float* __restrict__ delta_w, const float* __restrict__ out_w,
                             const float* __restrict__ Bp_w, const float* __restrict__ Cp_w,
                             const float* __restrict__ pn_w, const float* __restrict__ pn_b,
                             float* __restrict__ xp0, float* __restrict__ xp1,
                             float* __restrict__ xp2, float* __restrict__ wT)
{
    __shared__ float T[2080];
    __shared__ float MU[32], RS[32];
    __shared__ float CMU[64], CRS[64];
    int blk = blockIdx.x;
    int tid = threadIdx.x;
    if (blk < 2048) {
        int b = blk >> 10, h = (blk >> 5) & 31, w = blk & 31;
        if (tid < 64) {
            float2 p = ipart[b * 64 + tid];
            CMU[tid] = p.x;
            CRS[tid] = p.y;
        }
        __syncthreads();
        size_t bbase = (size_t)b * 2097152 + h * 1024 + w * 32;
        for (int e = tid; e < 2048; e += 256) {
            int c = e >> 5, d = e & 31;
            size_t i = bbase + (size_t)c * 32768 + d;
            float t2v = tmp2[i], x1v = x1[i];
            T[d * 65 + c] = x1v + lrelu_f((t2v - CMU[c]) * CRS[c]);
        }
        __syncthreads();
        {
            int d = tid >> 3, g = tid & 7;
            float s1 = 0.f, s2 = 0.f;
#pragma unroll
            for (int cc = 0; cc < 8; cc++) {
                float v = T[d * 65 + g * 8 + cc];
                s1 += v; s2 += v * v;
            }
#pragma unroll
            for (int o = 4; o > 0; o >>= 1) {
                s1 += __shfl_down_sync(0xffffffffu, s1, o);
                s2 += __shfl_down_sync(0xffffffffu, s2, o);
            }
            if (g == 0) {
                float mu = s1 * (1.f / 64.f);
                float var = s2 * (1.f / 64.f) - mu * mu;
                MU[d] = mu;
                RS[d] = rsqrtf(var + 1e-5f);
            }
        }
        __syncthreads();
        long base2 = (long)blk * XP_SEQ;
        long base1 = ((long)(b * 1024 + h * 32)) * XP_SEQ;
        long base0 = ((long)(b * 1024 + w * 32)) * XP_SEQ;
        if (tid < 64) {
            int d = tid & 31, wh = tid >> 5;
            float val = wh ? RS[d] : MU[d];
            xp2[base2 + wh * 32 + d] = val;
            xp1[base1 + (long)d * XP_SEQ + wh * 32 + w] = val;
            xp0[base0 + (long)d * XP_SEQ + wh * 32 + h] = val;
        }
        for (int e = tid; e < 2048; e += 256) {
            int d = e >> 6, c = e & 63;
            float v = T[d * 65 + c];
            xp2[base2 + 64 + e] = v;
            xp1[base1 + (long)d * XP_SEQ + 64 + w * 64 + c] = v;
            xp0[base0 + (long)d * XP_SEQ + 64 + h * 64 + c] = v;
        }
    } else if (blk < 2048 + 176) {
        int i = (blk - 2048) * 256 + tid;
        if (i < 8192)       wT[i] = left_w[(i & 127) * 64 + (i >> 7)];
        else if (i < 16384) { int j = i - 8192;  wT[i] = right_w[(j & 127) * 64 + (j >> 7)]; }
        else if (i < 32768) { int j = i - 16384; wT[i] = delta_w[(j & 127) * 128 + (j >> 7)]; }
        else if (i < 40960) { int j = i - 32768; wT[i] = out_w[(j & 63) * 128 + (j >> 6)] * pn_w[j >> 6]; }
        else if (i < 45056) {
            int j = i - 40960; int k = j >> 5, s = j & 31;
            wT[i] = (s < 16) ? Bp_w[s * 128 + k] : Cp_w[(s - 16) * 128 + k];
        }
    } else {
        if (tid < 64) {
            const float* Wp = out_w + tid * 128;
            float s = 0.f, bb = 0.f;
            for (int k = 0; k < 128; k++) {
                float wv = Wp[k];
                s = fmaf(wv, pn_w[k], s);
                bb = fmaf(wv, pn_b[k], bb);
            }
            wT[WT_S2 + tid] = s;
            wT[WT_B2 + tid] = bb;
        }
    }
}

// =================================================================================
// fused per-sequence Mamba (R15 version — measured best). grid (2048, 3), 256 thr.
// =================================================================================
#define MB_SMEM_FLOATS 17648
__global__ void __launch_bounds__(256, 3) mamba_kernel(
    const float* __restrict__ xp0, const float* __restrict__ xp1,
    const float* __restrict__ xp2,
    const float* __restrict__ ln_w,  const float* __restrict__ ln_b,
    const float* __restrict__ conv1d_w, const float* __restrict__ conv1d_b,
    const float* __restrict__ delta_b, const float* __restrict__ A_log,
    const float* __restrict__ wT,
    float* __restrict__ o0, float* __restrict__ o1, float* __restrict__ o2)
{
    extern __shared__ float sm[];
    float* XS   = sm;            // [64][36]
    float* XL   = sm + 2304;     // [128][36] left post conv+silu
    float* DS   = sm + 6912;     // [128][36] delta -> YS
    float* GA   = sm + 11520;    // [128][36] silu'd gate -> staging
    float* BS2  = sm + 16128;    // [32][16]
    float* CS2  = sm + 16656;    // [32][16] (bank offset 16)
    float* MUSD = sm + 17184;    // MU[32] | RSTD[32]
    float* A2S  = sm + 17248;    // [16]
    float* TAIL = sm + 17264;    // [128][3] raw-left t13..15 per column
    float* YS   = DS;
    float* GA2  = GA;

    int tid = threadIdx.x;
    int q = blockIdx.x;
    int axis = blockIdx.y;
    const float* xq = ((axis == 0) ? xp0 : (axis == 1) ? xp1 : xp2) + (long)q * XP_SEQ;
    float* oa = ((axis == 0) ? o0 : (axis == 1) ? o1 : o2) + (long)q * 2048;

    // ---- phase 0: gather + inline input-LN (header stats), transpose to XS ----
    if (tid < 16) A2S[tid] = -softplus_f(__ldg(A_log + tid)) * 1.44269504f;
    {
        const float4* xd4 = (const float4*)(xq + 64);
        for (int e = tid; e < 512; e += 256) {
            float4 v = __ldg(xd4 + e);
            int t = e >> 4, c4 = e & 15;
            float mu = __ldg(xq + t);
            float rs = __ldg(xq + 32 + t);
            float4 lw = __ldg((const float4*)ln_w + c4);
            float4 lb = __ldg((const float4*)ln_b + c4);
            int c0 = c4 * 4;
            XS[c0 * 36 + t]       = (v.x - mu) * rs * lw.x + lb.x;
            XS[(c0 + 1) * 36 + t] = (v.y - mu) * rs * lw.y + lb.y;
            XS[(c0 + 2) * 36 + t] = (v.z - mu) * rs * lw.z + lb.z;
            XS[(c0 + 3) * 36 + t] = (v.w - mu) * rs * lw.w + lb.w;
        }
    }
    __syncthreads();

    // ---- phase 2: left/right projections; right -> silu'd GA; left stays in regs ----
    int pairidx = tid & 63;
    int half = (tid >> 6) & 1;
    int which = tid >> 7;
    int c0 = 2 * pairidx;
    u64t accA[8], accB[8];
    {
        const float* wb = wT + (which ? WT_RIGHT : WT_LEFT);
#pragma unroll
        for (int j = 0; j < 8; j++) { accA[j] = 0ULL; accB[j] = 0ULL; }
#pragma unroll 4
        for (int k = 0; k < 64; k++) {
            float2 w2 = ((const float2*)(wb + k * 128))[pairidx];
            const ulonglong2* xr = (const ulonglong2*)(XS + k * 36) + half * 4;
            u64t waa = pk2(w2.x, w2.x), wbb = pk2(w2.y, w2.y);
#pragma unroll
            for (int j2 = 0; j2 < 4; j2++) {
                ulonglong2 xv = xr[j2];
                accA[2 * j2]     = fma2(xv.x, waa, accA[2 * j2]);
                accA[2 * j2 + 1] = fma2(xv.y, waa, accA[2 * j2 + 1]);
                accB[2 * j2]     = fma2(xv.x, wbb, accB[2 * j2]);
                accB[2 * j2 + 1] = fma2(xv.y, wbb, accB[2 * j2 + 1]);
            }
        }
        if (which == 1) {
            u64t* dA = (u64t*)(GA + c0 * 36) + half * 8;
            u64t* dB = (u64t*)(GA + (c0 + 1) * 36) + half * 8;
#pragma unroll
            for (int j = 0; j < 8; j++) {
                float a0, a1; upk2(accA[j], a0, a1);
                dA[j] = pk2(silu_f(a0), silu_f(a1));
                upk2(accB[j], a0, a1);
                dB[j] = pk2(silu_f(a0), silu_f(a1));
            }
        } else if (half == 0) {
            float x12, x13, x14, x15;
            upk2(accA[6], x12, x13); upk2(accA[7], x14, x15);
            TAIL[c0 * 3] = x13; TAIL[c0 * 3 + 1] = x14; TAIL[c0 * 3 + 2] = x15;
            upk2(accB[6], x12, x13); upk2(accB[7], x14, x15);
            TAIL[(c0 + 1) * 3] = x13; TAIL[(c0 + 1) * 3 + 1] = x14; TAIL[(c0 + 1) * 3 + 2] = x15;
        }
    }
    __syncthreads();

    // ---- phase 2b-lite: causal conv1d(k=4)+silu from REGISTERS -> XL ----
    if (which == 0) {
        float4 cwA = __ldg((const float4*)conv1d_w + c0);
        float4 cwB = __ldg((const float4*)conv1d_w + c0 + 1);
        float bA = __ldg(conv1d_b + c0), bB = __ldg(conv1d_b + c0 + 1);
        float pA1 = 0.f, pA2 = 0.f, pA3 = 0.f, pB1 = 0.f, pB2 = 0.f, pB3 = 0.f;
        if (half) {
            pA3 = TAIL[c0 * 3];       pA2 = TAIL[c0 * 3 + 1];       pA1 = TAIL[c0 * 3 + 2];
            pB3 = TAIL[(c0 + 1) * 3]; pB2 = TAIL[(c0 + 1) * 3 + 1]; pB1 = TAIL[(c0 + 1) * 3 + 2];
        }
        u64t* XA = (u64t*)(XL + c0 * 36 + half * 16);
        u64t* XB = (u64t*)(XL + (c0 + 1) * 36 + half * 16);
#pragma unroll
        for (int j = 0; j < 8; j++) {
            float a0, a1; upk2(accA[j], a0, a1);
            float s0 = fmaf(cwA.w, a0, bA); s0 = fmaf(cwA.z, pA1, s0);
            s0 = fmaf(cwA.y, pA2, s0); s0 = fmaf(cwA.x, pA3, s0);
            float s1 = fmaf(cwA.w, a1, bA); s1 = fmaf(cwA.z, a0, s1);
            s1 = fmaf(cwA.y, pA1, s1); s1 = fmaf(cwA.x, pA2, s1);
            XA[j] = pk2(silu_f(s0), silu_f(s1));
            pA3 = pA1; pA2 = a0; pA1 = a1;
            upk2(accB[j], a0, a1);
            s0 = fmaf(cwB.w, a0, bB); s0 = fmaf(cwB.z, pB1, s0);
            s0 = fmaf(cwB.y, pB2, s0); s0 = fmaf(cwB.x, pB3, s0);
            s1 = fmaf(cwB.w, a1, bB); s1 = fmaf(cwB.z, a0, s1);
            s1 = fmaf(cwB.y, pB1, s1); s1 = fmaf(cwB.x, pB2, s1);
            XB[j] = pk2(silu_f(s0), silu_f(s1));
            pB3 = pB1; pB2 = a0; pB1 = a1;
        }
    }
    __syncthreads();

    // ---- phase 3: delta proj (128 thr) + fused B/C proj (128 thr) ----
    if (tid < 128) {
        const float* wd = wT + WT_DELTA;
        u64t dcA[8], dcB[8];
#pragma unroll
        for (int j = 0; j < 8; j++) { dcA[j] = 0ULL; dcB[j] = 0ULL; }
#pragma unroll 4
        for (int k = 0; k < 128; k++) {
            float2 w2 = ((const float2*)(wd + k * 128))[pairidx];
            const ulonglong2* xr = (const ulonglong2*)(XL + k * 36) + half * 4;
            u64t waa = pk2(w2.x, w2.x), wbb = pk2(w2.y, w2.y);
#pragma unroll
            for (int j2 = 0; j2 < 4; j2++) {
                ulonglong2 xv = xr[j2];
                dcA[2 * j2]     = fma2(xv.x, waa, dcA[2 * j2]);
                dcA[2 * j2 + 1] = fma2(xv.y, waa, dcA[2 * j2 + 1]);
                dcB[2 * j2]     = fma2(xv.x, wbb, dcB[2 * j2]);
                dcB[2 * j2 + 1] = fma2(xv.y, wbb, dcB[2 * j2 + 1]);
            }
        }
        float b0 = __ldg(delta_b + c0), b1 = __ldg(delta_b + c0 + 1);
        float* d0 = DS + c0 * 36 + half * 16;
        float* d1 = DS + (c0 + 1) * 36 + half * 16;
#pragma unroll
        for (int j = 0; j < 8; j++) {
            float a0, a1; upk2(dcA[j], a0, a1);
            d0[2 * j]     = fminf(fmaxf(softplus_f(a0 + b0), 1e-4f), 10.f);
            d0[2 * j + 1] = fminf(fmaxf(softplus_f(a1 + b0), 1e-4f), 10.f);
            upk2(dcB[j], a0, a1);
            d1[2 * j]     = fminf(fmaxf(softplus_f(a0 + b1), 1e-4f), 10.f);
            d1[2 * j + 1] = fminf(fmaxf(softplus_f(a1 + b1), 1e-4f), 10.f);
        }
    } else {
        int idx = tid & 31;
        int seg = (tid >> 5) & 3;
        const float* wbc = wT + WT_BC;
        u64t acc[4];
#pragma unroll
        for (int j = 0; j < 4; j++) acc[j] = 0ULL;
#pragma unroll 4
        for (int k = 0; k < 128; k++) {
            float w = wbc[k * 32 + idx];
            const ulonglong2* xr = (const ulonglong2*)(XL + k * 36) + seg * 2;
            ulonglong2 xa = xr[0], xb = xr[1];
            u64t ww = pk2(w, w);
            acc[0] = fma2(xa.x, ww, acc[0]);
            acc[1] = fma2(xa.y, ww, acc[1]);
            acc[2] = fma2(xb.x, ww, acc[2]);
            acc[3] = fma2(xb.y, ww, acc[3]);
        }
        int s = idx & 15;
        float* DST = (idx < 16) ? BS2 : CS2;
#pragma unroll
        for (int j = 0; j < 4; j++) {
            float lo, hi; upk2(acc[j], lo, hi);
            int t = seg * 8 + 2 * j;
            DST[t * 16 + s]       = lo;
            DST[(t + 1) * 16 + s] = hi;
        }
    }
    __syncthreads();

    // ---- phase 4: selective scan (ex2 on MUFU), gate folded ----
    {
        int i = tid >> 1;
        int hlf = tid & 1;
        float h[8], a2l[8];
#pragma unroll
        for (int u2 = 0; u2 < 8; u2++) { h[u2] = 0.f; a2l[u2] = A2S[hlf * 8 + u2]; }
        const float* dsrow = DS + i * 36;
        const float* xlrow = XL + i * 36;
        const float* garow = GA + i * 36;
        for (int t2 = 0; t2 < 16; t2++) {
            float2 dd = *(const float2*)(dsrow + 2 * t2);
            float2 xx = *(const float2*)(xlrow + 2 * t2);
            float2 gg = *(const float2*)(garow + 2 * t2);
#pragma unroll
            for (int sub = 0; sub < 2; sub++) {
                int t = 2 * t2 + sub;
                float d  = sub ? dd.y : dd.x;
                float xv = sub ? xx.y : xx.x;
                float dx = d * xv;
                const float4* bp = (const float4*)(BS2 + t * 16 + hlf * 8);
                const float4* cp = (const float4*)(CS2 + t * 16 + hlf * 8);
                float4 b0 = bp[0], b1 = bp[1];
                float4 c0v = cp[0], c1v = cp[1];
                float bb[8] = {b0.x, b0.y, b0.z, b0.w, b1.x, b1.y, b1.z, b1.w};
                float cc[8] = {c0v.x, c0v.y, c0v.z, c0v.w, c1v.x, c1v.y, c1v.z, c1v.w};
                float part = 0.f;
#pragma unroll
                for (int u2 = 0; u2 < 8; u2++) {
                    float e = ex2_fast(d * a2l[u2]);
                    h[u2] = fmaf(e, h[u2], dx * bb[u2]);
                    part = fmaf(h[u2], cc[u2], part);
                }
                part += __shfl_xor_sync(0xffffffffu, part, 1);
                if (hlf == 0) YS[i * 36 + t] = part * (sub ? gg.y : gg.x);
            }
        }
    }
    __syncthreads();

    // ---- phase 5: post-LN stats over di=128 per timestep (reduce ONLY) ----
    {
        int t = tid >> 3, g = tid & 7;
        float s1 = 0.f, s2 = 0.f;
#pragma unroll
        for (int m = 0; m < 16; m++) {
            float vv = YS[(g + m * 8) * 36 + t];
            s1 += vv; s2 += vv * vv;
        }
#pragma unroll
        for (int o = 4; o > 0; o >>= 1) {
            s1 += __shfl_down_sync(0xffffffffu, s1, o);
            s2 += __shfl_down_sync(0xffffffffu, s2, o);
        }
        if (g == 0) {
            float mu = s1 * (1.f / 128.f);
            float var = s2 * (1.f / 128.f) - mu * mu;
            MUSD[t] = mu;
            MUSD[32 + t] = rsqrtf(var + 1e-5f);
        }
    }
    __syncthreads();

    // ---- phase 6: out projection on RAW gated-y + LN-fold -> GA2 -> STG ----
    {
        int cp = tid & 31, jq = tid >> 5;
        int cc0 = 2 * cp;
        const float* wo = wT + WT_OUT;
        u64t oA[2], oB[2];
        oA[0] = oA[1] = oB[0] = oB[1] = 0ULL;
#pragma unroll 4
        for (int k = 0; k < 128; k++) {
            float2 w2 = ((const float2*)(wo + k * 64))[cp];
            ulonglong2 xv = *((const ulonglong2*)(YS + k * 36) + jq);
            u64t waa = pk2(w2.x, w2.x), wbb = pk2(w2.y, w2.y);
            oA[0] = fma2(xv.x, waa, oA[0]);
            oA[1] = fma2(xv.y, waa, oA[1]);
            oB[0] = fma2(xv.x, wbb, oB[0]);
            oB[1] = fma2(xv.y, wbb, oB[1]);
        }
        float S2a = wT[WT_S2 + cc0], S2b = wT[WT_S2 + cc0 + 1];
        float B2a = wT[WT_B2 + cc0], B2b = wT[WT_B2 + cc0 + 1];
        __syncthreads();
#pragma unroll
        for (int j = 0; j < 2; j++) {
            int t = jq * 4 + 2 * j;
            float2 mus = *(const float2*)(MUSD + t);
            float2 rss = *(const float2*)(MUSD + 32 + t);
            float tx = mus.x * rss.x, ty = mus.y * rss.y;
            u64t rr = pk2(rss.x, rss.y);
            u64t offA = pk2(fmaf(-tx, S2a, B2a), fmaf(-ty, S2a, B2a));
            u64t offB = pk2(fmaf(-tx, S2b, B2b), fmaf(-ty, S2b, B2b));
            u64t vA = fma2(oA[j], rr, offA);
            u64t vB = fma2(oB[j], rr, offB);
            float a0, a1; upk2(vA, a0, a1);
            GA2[t * 64 + cc0]       = a0;
            GA2[(t + 1) * 64 + cc0] = a1;
            upk2(vB, a0, a1);
            GA2[t * 64 + cc0 + 1]       = a0;
            GA2[(t + 1) * 64 + cc0 + 1] = a1;
        }
    }
    __syncthreads();
    for (int e = tid; e < 512; e += 256)
        ((float4*)oa)[e] = ((const float4*)GA2)[e];
}

// ---------------- final combine: identity + rs * softmax(axis_w) . outputs -----
__global__ void final_kernel(const float* __restrict__ x,
                             const float* __restrict__ o0, const float* __restrict__ o1,
                             const float* __restrict__ o2,
                             const float* __restrict__ rs, const float* __restrict__ axis_w,
                             float* __restrict__ out)
{
    __shared__ float S[2080];
    int blk = blockIdx.x, tid = threadIdx.x;
    int b = blk >> 10, h = (blk >> 5) & 31, w = blk & 31;
    float a0 = axis_w[0], a1 = axis_w[1], a2 = axis_w[2];
    float m = fmaxf(a0, fmaxf(a1, a2));
    float e0 = __expf(a0 - m), e1 = __expf(a1 - m), e2 = __expf(a2 - m);
    float r = rs[0] / (e0 + e1 + e2);
    float w0 = r * e0, w1 = r * e1, w2 = r * e2;
    long s2 = (long)blk * 2048;
    long s1 = ((long)(b * 1024 + h * 32)) * 2048 + w * 64;
    long s0 = ((long)(b * 1024 + w * 32)) * 2048 + h * 64;
    for (int e = tid; e < 2048; e += 256) {
        int d = e >> 6, c = e & 63;
        S[d * 65 + c] = w0 * o0[s0 + (long)d * 2048 + c]
                      + w1 * o1[s1 + (long)d * 2048 + c]
                      + w2 * o2[s2 + e];
    }
    __syncthreads();
    const float* xb = x + (size_t)b * 2097152 + h * 1024 + w * 32;
    float* ob = out + (size_t)b * 2097152 + h * 1024 + w * 32;
    for (int e = tid; e < 2048; e += 256) {
        int c = e >> 5, d = e & 31;
        ob[(size_t)c * 32768 + d] = xb[(size_t)c * 32768 + d] + S[d * 65 + c];
    }
}

// ---------------- launch ----------------
extern "C" void kernel_launch(void* const* d_in, const int* in_sizes, int n_in,
                              void* d_out, int out_size) {
    (void)in_sizes; (void)n_in; (void)out_size;
    const float* x        = (const float*)d_in[0];
    const float* cr1_w    = (const float*)d_in[1];
    const float* cr1_b    = (const float*)d_in[2];
    const float* cr2_w    = (const float*)d_in[3];
    const float* cr2_b    = (const float*)d_in[4];
    const float* ln_w     = (const float*)d_in[5];
    const float* ln_b     = (const float*)d_in[6];
    const float* left_w   = (const float*)d_in[7];
    const float* conv1d_w = (const float*)d_in[8];
    const float* conv1d_b = (const float*)d_in[9];
    const float* delta_w  = (const float*)d_in[10];
    const float* delta_b  = (const float*)d_in[11];
    const float* Bp_w     = (const float*)d_in[12];
    const float* Cp_w     = (const float*)d_in[13];
    const float* A_log    = (const float*)d_in[14];
    const float* right_w  = (const float*)d_in[15];
    const float* pn_w     = (const float*)d_in[16];
    const float* pn_b     = (const float*)d_in[17];
    const float* out_w    = (const float*)d_in[18];
    const float* res_scl  = (const float*)d_in[19];
    const float* axis_w   = (const float*)d_in[20];
    float* out = (float*)d_out;

    float *tmp, *x1, *xp0, *xp1, *xp2, *o0, *o1, *o2, *wT, *cwT;
    float2* ipart;
    cudaGetSymbolAddress((void**)&tmp, g_tmp);
    cudaGetSymbolAddress((void**)&x1, g_x1);
    cudaGetSymbolAddress((void**)&xp0, g_xp0);
    cudaGetSymbolAddress((void**)&xp1, g_xp1);
    cudaGetSymbolAddress((void**)&xp2, g_xp2);
    cudaGetSymbolAddress((void**)&o0, g_o0);
    cudaGetSymbolAddress((void**)&o1, g_o1);
    cudaGetSymbolAddress((void**)&o2, g_o2);
    cudaGetSymbolAddress((void**)&wT, g_wT);
    cudaGetSymbolAddress((void**)&cwT, g_cwT);
    cudaGetSymbolAddress((void**)&ipart, g_ipart);

    cudaFuncSetAttribute(conv3d_kernel, cudaFuncAttributeMaxDynamicSharedMemorySize,
                         CONV_SMEM_BYTES);
    cudaFuncSetAttribute(mamba_kernel, cudaFuncAttributeMaxDynamicSharedMemorySize,
                         MB_SMEM_FLOATS * (int)sizeof(float));

    // 1: conv weight transpose
    cwT_kernel<<<(221184 + 255) / 256, 256>>>(cr1_w, cr2_w, cwT);

    dim3 cg(32, 4, 2);
    // 2: conv1
    conv3d_kernel<<<cg, 256, CONV_SMEM_BYTES>>>(x, cwT, cr1_b, tmp);
    // 3: inorm1 (full: x1 = x + lrelu(norm(tmp)))
    inorm_res_kernel<<<128, 1024>>>(tmp, x, x1);
    // 4: conv2  (ncu capture slot)
    conv3d_kernel<<<cg, 256, CONV_SMEM_BYTES>>>(x1, cwT + 110592, cr2_b, tmp);
    // 5: inorm2 stats only
    inorm_stats_kernel<<<128, 1024>>>(tmp, ipart);
    // 6: trans (x2 inline + per-voxel LN stats + fold constants)
    trans_kernel<<<2048 + 177, 256>>>(tmp, x1, ipart, left_w, right_w, delta_w, out_w,
                                      Bp_w, Cp_w, pn_w, pn_b, xp0, xp1, xp2, wT);
    // 7: mamba
    mamba_kernel<<<dim3(2048, 3), 256, MB_SMEM_FLOATS * (int)sizeof(float)>>>(
        xp0, xp1, xp2, ln_w, ln_b, conv1d_w, conv1d_b, delta_b, A_log,
        wT, o0, o1, o2);
    // 8: final
    final_kernel<<<2048, 256>>>(x, o0, o1, o2, res_scl, axis_w, out);
}

// round 17
// speedup vs baseline: 1.0294x; 1.0294x over previous
#include <cuda_runtime.h>
#include <math.h>

// ---------------- scratch (static device globals; no allocation) ----------------
#define NVOX 4194304  // 2*64*32*32*32
#define XP_SEQ 2112   // 64-float LN-stats header + 2048 data
#define XP_TOTAL (2048 * XP_SEQ)
static __device__ float g_tmp[NVOX];
static __device__ float g_x1[NVOX];
static __device__ float g_xp0[XP_TOTAL];
static __device__ float g_xp1[XP_TOTAL];
static __device__ float g_xp2[XP_TOTAL];
static __device__ float g_o0[NVOX];
static __device__ float g_o1[NVOX];
static __device__ float g_o2[NVOX];
static __device__ float g_cwT[2 * 110592];   // conv weights [(ci*27+kk)*64 + co]
static __device__ float2 g_ipart[128];       // inorm2 stats (mu, rstd) per (b*64+c)

// transposed weights: left 8192 | right 8192 | delta 16384 | out' 8192 | bc 4096 |
// S2 64 | B2 64
#define WT_LEFT  0
#define WT_RIGHT 8192
#define WT_DELTA 16384
#define WT_OUT   32768
#define WT_BC    40960
#define WT_S2    45056
#define WT_B2    45120
#define WT_TOTAL 45184
static __device__ float g_wT[WT_TOTAL];

typedef unsigned long long u64t;

// ---------------- f32x2 packed-FMA helpers (Blackwell FFMA2, PTX-only) ----------
__device__ __forceinline__ u64t pk2(float lo, float hi) {
    u64t r; asm("mov.b64 %0, {%1,%2};" : "=l"(r) : "f"(lo), "f"(hi)); return r;
}
__device__ __forceinline__ void upk2(u64t v, float& lo, float& hi) {
    asm("mov.b64 {%0,%1}, %2;" : "=f"(lo), "=f"(hi) : "l"(v));
}
__device__ __forceinline__ u64t fma2(u64t a, u64t b, u64t c) {
    u64t d; asm("fma.rn.f32x2 %0, %1, %2, %3;" : "=l"(d) : "l"(a), "l"(b), "l"(c)); return d;
}

// ---------------- scalar helpers ----------------
__device__ __forceinline__ float softplus_f(float x) {
    return fmaxf(x, 0.f) + log1pf(__expf(-fabsf(x)));
}
__device__ __forceinline__ float silu_f(float x) {
    return x / (1.f + __expf(-x));
}
__device__ __forceinline__ float ex2_fast(float x) {   // MUFU pipe
    float r; asm("ex2.approx.ftz.f32 %0, %1;" : "=f"(r) : "f"(x)); return r;
}
__device__ __forceinline__ float lrelu_f(float a) {
    return a >= 0.f ? a : 0.01f * a;
}
__device__ __forceinline__ void cpa16(unsigned int dst, const void* src) {
    asm volatile("cp.async.cg.shared.global [%0], [%1], 16;" :: "r"(dst), "l"(src));
}

// ---------------- conv weight transpose: cw[co][ci][kk] -> [(ci*27+kk)*64+co] ----
__global__ void cwT_kernel(const float* __restrict__ cw1, const float* __restrict__ cw2,
                           float* __restrict__ gcw) {
    int i = blockIdx.x * 256 + threadIdx.x;   // 0 .. 221183
    if (i < 110592) {
        int co = i & 63, r = i >> 6;
        gcw[i] = cw1[co * 1728 + r];
    } else if (i < 221184) {
        int j = i - 110592;
        int co = j & 63, r = j >> 6;
        gcw[i] = cw2[co * 1728 + r];
    }
}

// =================================================================================
// conv3d 3x3x3, C=64->64, +bias. grid (32 h, 4 co-groups of 16, 2 b), block 256.
// cp.async double-buffered 2-ci slabs. (R11/R15 version — measured best: 285us.)
// =================================================================================
#define CONV_SMEM_BYTES ((2 * 8160 + 2 * 864) * 4)
__global__ void __launch_bounds__(256, 2) conv3d_kernel(
    const float* __restrict__ xin, const float* __restrict__ gcw,
    const float* __restrict__ cb, float* __restrict__ out)
{
    extern __shared__ float cs[];
    float* TIN = cs;                 // [2 buf][2 ci][3 kh][34 rows][40]
    float* WS  = cs + 16320;         // [2 buf][2 ci][27 kk][16 co]

    int tid = threadIdx.x;
    int lane = tid & 31, wid = tid >> 5;
    int h = blockIdx.x;
    int cog = blockIdx.y;            // co base = cog*16
    int b = blockIdx.z;

    unsigned int tin_u = (unsigned int)__cvta_generic_to_shared(TIN);
    unsigned int ws_u  = (unsigned int)__cvta_generic_to_shared(WS);

    for (int idx = tid; idx < 16320; idx += 256) TIN[idx] = 0.f;
    __syncthreads();

    auto load_slab = [&](int s, int buf) {
#pragma unroll
        for (int ci2 = 0; ci2 < 2; ci2++) {
            int ci = 2 * s + ci2;
            const float* src_base = xin + ((size_t)(b * 64 + ci)) * 32768;
            unsigned int dstb = tin_u + (unsigned int)(buf * 8160 + ci2 * 4080) * 4u;
#pragma unroll
            for (int r = 0; r < 3; r++) {
                int j = r * 256 + tid;
                int kh = j >> 8, qq = j & 255;
                int w = qq >> 3, seg = qq & 7;
                int hh = h + kh - 1;
                if (hh >= 0 && hh < 32) {
                    cpa16(dstb + (unsigned int)(kh * 1360 + (w + 1) * 40 + 4 + seg * 4) * 4u,
                          src_base + hh * 1024 + w * 32 + seg * 4);
                }
            }
        }
        if (tid < 216) {
            int ci2 = tid / 108, r = tid % 108;
            int kk = r >> 2, qd = r & 3;
            int ci = 2 * s + ci2;
            cpa16(ws_u + (unsigned int)(buf * 864 + ci2 * 432 + kk * 16 + qd * 4) * 4u,
                  gcw + (size_t)((ci * 27 + kk) * 16 + cog * 4 + qd) * 4);
        }
        asm volatile("cp.async.commit_group;" ::: "memory");
    };

    u64t acc2[32];
#pragma unroll
    for (int i = 0; i < 32; i++) acc2[i] = 0ULL;

    load_slab(0, 0);
    asm volatile("cp.async.wait_group 0;" ::: "memory");
    __syncthreads();

    for (int s = 0; s < 32; s++) {
        int cur = s & 1;
        if (s < 31) load_slab(s + 1, cur ^ 1);    // async, overlaps compute
#pragma unroll
        for (int ci2 = 0; ci2 < 2; ci2++) {
            const float* tb = TIN + cur * 8160 + ci2 * 4080;
            const ulonglong2* wb = (const ulonglong2*)(WS + cur * 864 + ci2 * 432);
#pragma unroll
            for (int kh = 0; kh < 3; kh++) {
                const float* tkh = tb + kh * 1360;
#pragma unroll
                for (int kw = 0; kw < 3; kw++) {
#pragma unroll
                    for (int kd = 0; kd < 3; kd++) {
                        int kk = kh * 9 + kw * 3 + kd;
                        ulonglong2 wq0 = wb[kk * 4];
                        ulonglong2 wq1 = wb[kk * 4 + 1];
                        ulonglong2 wq2 = wb[kk * 4 + 2];
                        ulonglong2 wq3 = wb[kk * 4 + 3];
#pragma unroll
                        for (int ws = 0; ws < 4; ws++) {
                            float v = tkh[(ws * 8 + wid + kw) * 40 + 3 + lane + kd];
                            u64t vv = pk2(v, v);
                            acc2[ws * 8 + 0] = fma2(vv, wq0.x, acc2[ws * 8 + 0]);
                            acc2[ws * 8 + 1] = fma2(vv, wq0.y, acc2[ws * 8 + 1]);
                            acc2[ws * 8 + 2] = fma2(vv, wq1.x, acc2[ws * 8 + 2]);
                            acc2[ws * 8 + 3] = fma2(vv, wq1.y, acc2[ws * 8 + 3]);
                            acc2[ws * 8 + 4] = fma2(vv, wq2.x, acc2[ws * 8 + 4]);
                            acc2[ws * 8 + 5] = fma2(vv, wq2.y, acc2[ws * 8 + 5]);
                            acc2[ws * 8 + 6] = fma2(vv, wq3.x, acc2[ws * 8 + 6]);
                            acc2[ws * 8 + 7] = fma2(vv, wq3.y, acc2[ws * 8 + 7]);
                        }
                    }
                }
            }
        }
        asm volatile("cp.async.wait_group 0;" ::: "memory");
        __syncthreads();
    }

    float bias[16];
#pragma unroll
    for (int e = 0; e < 16; e++) bias[e] = cb[cog * 16 + e];
#pragma unroll
    for (int ws = 0; ws < 4; ws++) {
        int w = ws * 8 + wid;
        size_t o = ((size_t)(b * 64 + cog * 16)) * 32768 + (size_t)h * 1024 + w * 32 + lane;
#pragma unroll
        for (int p = 0; p < 8; p++) {
            float alo, ahi;
            upk2(acc2[ws * 8 + p], alo, ahi);
            out[o + (size_t)(p * 2) * 32768]     = alo + bias[p * 2];
            out[o + (size_t)(p * 2 + 1) * 32768] = ahi + bias[p * 2 + 1];
        }
    }
}

// ---------------- InstanceNorm3d + LeakyReLU(0.01) + residual (1024 thr) --------
__global__ void inorm_res_kernel(const float* __restrict__ y,
                                 const float* __restrict__ res,
                                 float* __restrict__ out) {
    int bc = blockIdx.x;
    const float4* yp = (const float4*)(y + (size_t)bc * 32768);
    int tid = threadIdx.x;
    int lane = tid & 31, wid = tid >> 5;
    float s1 = 0.f, s2 = 0.f;
    for (int i = tid; i < 8192; i += 1024) {
        float4 v = yp[i];
        s1 += v.x + v.y + v.z + v.w;
        s2 += v.x * v.x + v.y * v.y + v.z * v.z + v.w * v.w;
    }
#pragma unroll
    for (int o = 16; o > 0; o >>= 1) {
        s1 += __shfl_xor_sync(0xffffffffu, s1, o);
        s2 += __shfl_xor_sync(0xffffffffu, s2, o);
    }
    __shared__ float r1[32], r2[32];
    __shared__ float mu_s, rstd_s;
    if (lane == 0) { r1[wid] = s1; r2[wid] = s2; }
    __syncthreads();
    if (tid < 32) {
        float a = r1[tid], c = r2[tid];
#pragma unroll
        for (int o = 16; o > 0; o >>= 1) {
            a += __shfl_xor_sync(0xffffffffu, a, o);
            c += __shfl_xor_sync(0xffffffffu, c, o);
        }
        if (tid == 0) {
            float mu = a * (1.f / 32768.f);
            float var = c * (1.f / 32768.f) - mu * mu;
            mu_s = mu; rstd_s = rsqrtf(var + 1e-5f);
        }
    }
    __syncthreads();
    float mu = mu_s, rstd = rstd_s;
    const float4* rp = (const float4*)(res + (size_t)bc * 32768);
    float4* op = (float4*)(out + (size_t)bc * 32768);
    for (int i = tid; i < 8192; i += 1024) {
        float4 v = yp[i]; float4 r = rp[i]; float4 o;
        float a;
        a = (v.x - mu) * rstd; o.x = r.x + lrelu_f(a);
        a = (v.y - mu) * rstd; o.y = r.y + lrelu_f(a);
        a = (v.z - mu) * rstd; o.z = r.z + lrelu_f(a);
        a = (v.w - mu) * rstd; o.w = r.w + lrelu_f(a);
        op[i] = o;
    }
}

// ---------------- inorm2 stats only: (mu, rstd) per (b,c) ----------------------
__global__ void inorm_stats_kernel(const float* __restrict__ y, float2* __restrict__ part) {
    int bc = blockIdx.x;
    const float4* yp = (const float4*)(y + (size_t)bc * 32768);
    int tid = threadIdx.x;
    int lane = tid & 31, wid = tid >> 5;
    float s1 = 0.f, s2 = 0.f;
    for (int i = tid; i < 8192; i += 1024) {
        float4 v = yp[i];
        s1 += v.x + v.y + v.z + v.w;
        s2 += v.x * v.x + v.y * v.y + v.z * v.z + v.w * v.w;
    }
#pragma unroll
    for (int o = 16; o > 0; o >>= 1) {
        s1 += __shfl_xor_sync(0xffffffffu, s1, o);
        s2 += __shfl_xor_sync(0xffffffffu, s2, o);
    }
    __shared__ float r1[32], r2[32];
    if (lane == 0) { r1[wid] = s1; r2[wid] = s2; }
    __syncthreads();
    if (tid < 32) {
        float a = r1[tid], c = r2[tid];
#pragma unroll
        for (int o = 16; o > 0; o >>= 1) {
            a += __shfl_xor_sync(0xffffffffu, a, o);
            c += __shfl_xor_sync(0xffffffffu, c, o);
        }
        if (tid == 0) {
            float mu = a * (1.f / 32768.f);
            float var = c * (1.f / 32768.f) - mu * mu;
            part[bc] = make_float2(mu, rsqrtf(var + 1e-5f));
        }
    }
}

// =================================================================================
// trans: x2 computed INLINE from (tmp, x1, inorm2 stats); writes 3 axis copies
// [seq][64-hdr: mu32|rs32][t][c] with per-voxel LN stats. Also weight transposes.
// grid 2048 + 177, block 256.
// =================================================================================
__global__ void trans_kernel(const float* __restrict__ tmp2, const float* __restrict__ x1,
                             const float2* __restrict__ ipart,
                             const float* __restrict__ left_w, const float* __restrict__ right_w,
                             const float* __restrict__ delta_w, const float* __restrict__ out_w,
                             const float* __restrict__ Bp_w, const float* __restrict__ Cp_w,
                             const float* __restrict__ pn_w, const float* __restrict__ pn_b,
                             float* __restrict__ xp0, float* __restrict__ xp1,
                             float* __restrict__ xp2, float* __restrict__ wT)
{
    __shared__ float T[2080];
    __shared__ float MU[32], RS[32];
    __shared__ float CMU[64], CRS[64];
    int blk = blockIdx.x;
    int tid = threadIdx.x;
    if (blk < 2048) {
        int b = blk >> 10, h = (blk >> 5) & 31, w = blk & 31;
        if (tid < 64) {
            float2 p = ipart[b * 64 + tid];
            CMU[tid] = p.x;
            CRS[tid] = p.y;
        }
        __syncthreads();
        size_t bbase = (size_t)b * 2097152 + h * 1024 + w * 32;
        for (int e = tid; e < 2048; e += 256) {
            int c = e >> 5, d = e & 31;
            size_t i = bbase + (size_t)c * 32768 + d;
            float t2v = tmp2[i], x1v = x1[i];
            T[d * 65 + c] = x1v + lrelu_f((t2v - CMU[c]) * CRS[c]);
        }
        __syncthreads();
        {
            int d = tid >> 3, g = tid & 7;
            float s1 = 0.f, s2 = 0.f;
#pragma unroll
            for (int cc = 0; cc < 8; cc++) {
                float v = T[d * 65 + g * 8 + cc];
                s1 += v; s2 += v * v;
            }
#pragma unroll
            for (int o = 4; o > 0; o >>= 1) {
                s1 += __shfl_down_sync(0xffffffffu, s1, o);
                s2 += __shfl_down_sync(0xffffffffu, s2, o);
            }
            if (g == 0) {
                float mu = s1 * (1.f / 64.f);
                float var = s2 * (1.f / 64.f) - mu * mu;
                MU[d] = mu;
                RS[d] = rsqrtf(var + 1e-5f);
            }
        }
        __syncthreads();
        long base2 = (long)blk * XP_SEQ;
        long base1 = ((long)(b * 1024 + h * 32)) * XP_SEQ;
        long base0 = ((long)(b * 1024 + w * 32)) * XP_SEQ;
        if (tid < 64) {
            int d = tid & 31, wh = tid >> 5;
            float val = wh ? RS[d] : MU[d];
            xp2[base2 + wh * 32 + d] = val;
            xp1[base1 + (long)d * XP_SEQ + wh * 32 + w] = val;
            xp0[base0 + (long)d * XP_SEQ + wh * 32 + h] = val;
        }
        for (int e = tid; e < 2048; e += 256) {
            int d = e >> 6, c = e & 63;
            float v = T[d * 65 + c];
            xp2[base2 + 64 + e] = v;
            xp1[base1 + (long)d * XP_SEQ + 64 + w * 64 + c] = v;
            xp0[base0 + (long)d * XP_SEQ + 64 + h * 64 + c] = v;
        }
    } else if (blk < 2048 + 176) {
        int i = (blk - 2048) * 256 + tid;
        if (i < 8192)       wT[i] = left_w[(i & 127) * 64 + (i >> 7)];
        else if (i < 16384) { int j = i - 8192;  wT[i] = right_w[(j & 127) * 64 + (j >> 7)]; }
        else if (i < 32768) { int j = i - 16384; wT[i] = delta_w[(j & 127) * 128 + (j >> 7)]; }
        else if (i < 40960) { int j = i - 32768; wT[i] = out_w[(j & 63) * 128 + (j >> 6)] * pn_w[j >> 6]; }
        else if (i < 45056) {
            int j = i - 40960; int k = j >> 5, s = j & 31;
            wT[i] = (s < 16) ? Bp_w[s * 128 + k] : Cp_w[(s - 16) * 128 + k];
        }
    } else {
        if (tid < 64) {
            const float* Wp = out_w + tid * 128;
            float s = 0.f, bb = 0.f;
            for (int k = 0; k < 128; k++) {
                float wv = Wp[k];
                s = fmaf(wv, pn_w[k], s);
                bb = fmaf(wv, pn_b[k], bb);
            }
            wT[WT_S2 + tid] = s;
            wT[WT_B2 + tid] = bb;
        }
    }
}

// =================================================================================
// fused per-sequence Mamba (R15 version — measured best). grid (2048, 3), 256 thr.
// =================================================================================
#define MB_SMEM_FLOATS 17648
__global__ void __launch_bounds__(256, 3) mamba_kernel(
    const float* __restrict__ xp0, const float* __restrict__ xp1,
    const float* __restrict__ xp2,
    const float* __restrict__ ln_w,  const float* __restrict__ ln_b,
    const float* __restrict__ conv1d_w, const float* __restrict__ conv1d_b,
    const float* __restrict__ delta_b, const float* __restrict__ A_log,
    const float* __restrict__ wT,
    float* __restrict__ o0, float* __restrict__ o1, float* __restrict__ o2)
{
    extern __shared__ float sm[];
    float* XS   = sm;            // [64][36]
    float* XL   = sm + 2304;     // [128][36] left post conv+silu
    float* DS   = sm + 6912;     // [128][36] delta -> YS
    float* GA   = sm + 11520;    // [128][36] silu'd gate -> staging
    float* BS2  = sm + 16128;    // [32][16]
    float* CS2  = sm + 16656;    // [32][16] (bank offset 16)
    float* MUSD = sm + 17184;    // MU[32] | RSTD[32]
    float* A2S  = sm + 17248;    // [16]
    float* TAIL = sm + 17264;    // [128][3] raw-left t13..15 per column
    float* YS   = DS;
    float* GA2  = GA;

    int tid = threadIdx.x;
    int q = blockIdx.x;
    int axis = blockIdx.y;
    const float* xq = ((axis == 0) ? xp0 : (axis == 1) ? xp1 : xp2) + (long)q * XP_SEQ;
    float* oa = ((axis == 0) ? o0 : (axis == 1) ? o1 : o2) + (long)q * 2048;

    // ---- phase 0: gather + inline input-LN (header stats), transpose to XS ----
    if (tid < 16) A2S[tid] = -softplus_f(__ldg(A_log + tid)) * 1.44269504f;
    {
        const float4* xd4 = (const float4*)(xq + 64);
        for (int e = tid; e < 512; e += 256) {
            float4 v = __ldg(xd4 + e);
            int t = e >> 4, c4 = e & 15;
            float mu = __ldg(xq + t);
            float rs = __ldg(xq + 32 + t);
            float4 lw = __ldg((const float4*)ln_w + c4);
            float4 lb = __ldg((const float4*)ln_b + c4);
            int c0 = c4 * 4;
            XS[c0 * 36 + t]       = (v.x - mu) * rs * lw.x + lb.x;
            XS[(c0 + 1) * 36 + t] = (v.y - mu) * rs * lw.y + lb.y;
            XS[(c0 + 2) * 36 + t] = (v.z - mu) * rs * lw.z + lb.z;
            XS[(c0 + 3) * 36 + t] = (v.w - mu) * rs * lw.w + lb.w;
        }
    }
    __syncthreads();

    // ---- phase 2: left/right projections; right -> silu'd GA; left stays in regs ----
    int pairidx = tid & 63;
    int half = (tid >> 6) & 1;
    int which = tid >> 7;
    int c0 = 2 * pairidx;
    u64t accA[8], accB[8];
    {
        const float* wb = wT + (which ? WT_RIGHT : WT_LEFT);
#pragma unroll
        for (int j = 0; j < 8; j++) { accA[j] = 0ULL; accB[j] = 0ULL; }
#pragma unroll 4
        for (int k = 0; k < 64; k++) {
            float2 w2 = ((const float2*)(wb + k * 128))[pairidx];
            const ulonglong2* xr = (const ulonglong2*)(XS + k * 36) + half * 4;
            u64t waa = pk2(w2.x, w2.x), wbb = pk2(w2.y, w2.y);
#pragma unroll
            for (int j2 = 0; j2 < 4; j2++) {
                ulonglong2 xv = xr[j2];
                accA[2 * j2]     = fma2(xv.x, waa, accA[2 * j2]);
                accA[2 * j2 + 1] = fma2(xv.y, waa, accA[2 * j2 + 1]);
                accB[2 * j2]     = fma2(xv.x, wbb, accB[2 * j2]);
                accB[2 * j2 + 1] = fma2(xv.y, wbb, accB[2 * j2 + 1]);
            }
        }
        if (which == 1) {
            u64t* dA = (u64t*)(GA + c0 * 36) + half * 8;
            u64t* dB = (u64t*)(GA + (c0 + 1) * 36) + half * 8;
#pragma unroll
            for (int j = 0; j < 8; j++) {
                float a0, a1; upk2(accA[j], a0, a1);
                dA[j] = pk2(silu_f(a0), silu_f(a1));
                upk2(accB[j], a0, a1);
                dB[j] = pk2(silu_f(a0), silu_f(a1));
            }
        } else if (half == 0) {
            float x12, x13, x14, x15;
            upk2(accA[6], x12, x13); upk2(accA[7], x14, x15);
            TAIL[c0 * 3] = x13; TAIL[c0 * 3 + 1] = x14; TAIL[c0 * 3 + 2] = x15;
            upk2(accB[6], x12, x13); upk2(accB[7], x14, x15);
            TAIL[(c0 + 1) * 3] = x13; TAIL[(c0 + 1) * 3 + 1] = x14; TAIL[(c0 + 1) * 3 + 2] = x15;
        }
    }
    __syncthreads();

    // ---- phase 2b-lite: causal conv1d(k=4)+silu from REGISTERS -> XL ----
    if (which == 0) {
        float4 cwA = __ldg((const float4*)conv1d_w + c0);
        float4 cwB = __ldg((const float4*)conv1d_w + c0 + 1);
        float bA = __ldg(conv1d_b + c0), bB = __ldg(conv1d_b + c0 + 1);
        float pA1 = 0.f, pA2 = 0.f, pA3 = 0.f, pB1 = 0.f, pB2 = 0.f, pB3 = 0.f;
        if (half) {
            pA3 = TAIL[c0 * 3];       pA2 = TAIL[c0 * 3 + 1];       pA1 = TAIL[c0 * 3 + 2];
            pB3 = TAIL[(c0 + 1) * 3]; pB2 = TAIL[(c0 + 1) * 3 + 1]; pB1 = TAIL[(c0 + 1) * 3 + 2];
        }
        u64t* XA = (u64t*)(XL + c0 * 36 + half * 16);
        u64t* XB = (u64t*)(XL + (c0 + 1) * 36 + half * 16);
#pragma unroll
        for (int j = 0; j < 8; j++) {
            float a0, a1; upk2(accA[j], a0, a1);
            float s0 = fmaf(cwA.w, a0, bA); s0 = fmaf(cwA.z, pA1, s0);
            s0 = fmaf(cwA.y, pA2, s0); s0 = fmaf(cwA.x, pA3, s0);
            float s1 = fmaf(cwA.w, a1, bA); s1 = fmaf(cwA.z, a0, s1);
            s1 = fmaf(cwA.y, pA1, s1); s1 = fmaf(cwA.x, pA2, s1);
            XA[j] = pk2(silu_f(s0), silu_f(s1));
            pA3 = pA1; pA2 = a0; pA1 = a1;
            upk2(accB[j], a0, a1);
            s0 = fmaf(cwB.w, a0, bB); s0 = fmaf(cwB.z, pB1, s0);
            s0 = fmaf(cwB.y, pB2, s0); s0 = fmaf(cwB.x, pB3, s0);
            s1 = fmaf(cwB.w, a1, bB); s1 = fmaf(cwB.z, a0, s1);
            s1 = fmaf(cwB.y, pB1, s1); s1 = fmaf(cwB.x, pB2, s1);
            XB[j] = pk2(silu_f(s0), silu_f(s1));
            pB3 = pB1; pB2 = a0; pB1 = a1;
        }
    }
    __syncthreads();

    // ---- phase 3: delta proj (128 thr) + fused B/C proj (128 thr) ----
    if (tid < 128) {
        const float* wd = wT + WT_DELTA;
        u64t dcA[8], dcB[8];
#pragma unroll
        for (int j = 0; j < 8; j++) { dcA[j] = 0ULL; dcB[j] = 0ULL; }
#pragma unroll 4
        for (int k = 0; k < 128; k++) {
            float2 w2 = ((const float2*)(wd + k * 128))[pairidx];
            const ulonglong2* xr = (const ulonglong2*)(XL + k * 36) + half * 4;
            u64t waa = pk2(w2.x, w2.x), wbb = pk2(w2.y, w2.y);
#pragma unroll
            for (int j2 = 0; j2 < 4; j2++) {
                ulonglong2 xv = xr[j2];
                dcA[2 * j2]     = fma2(xv.x, waa, dcA[2 * j2]);
                dcA[2 * j2 + 1] = fma2(xv.y, waa, dcA[2 * j2 + 1]);
                dcB[2 * j2]     = fma2(xv.x, wbb, dcB[2 * j2]);
                dcB[2 * j2 + 1] = fma2(xv.y, wbb, dcB[2 * j2 + 1]);
            }
        }
        float b0 = __ldg(delta_b + c0), b1 = __ldg(delta_b + c0 + 1);
        float* d0 = DS + c0 * 36 + half * 16;
        float* d1 = DS + (c0 + 1) * 36 + half * 16;
#pragma unroll
        for (int j = 0; j < 8; j++) {
            float a0, a1; upk2(dcA[j], a0, a1);
            d0[2 * j]     = fminf(fmaxf(softplus_f(a0 + b0), 1e-4f), 10.f);
            d0[2 * j + 1] = fminf(fmaxf(softplus_f(a1 + b0), 1e-4f), 10.f);
            upk2(dcB[j], a0, a1);
            d1[2 * j]     = fminf(fmaxf(softplus_f(a0 + b1), 1e-4f), 10.f);
            d1[2 * j + 1] = fminf(fmaxf(softplus_f(a1 + b1), 1e-4f), 10.f);
        }
    } else {
        int idx = tid & 31;
        int seg = (tid >> 5) & 3;
        const float* wbc = wT + WT_BC;
        u64t acc[4];
#pragma unroll
        for (int j = 0; j < 4; j++) acc[j] = 0ULL;
#pragma unroll 4
        for (int k = 0; k < 128; k++) {
            float w = wbc[k * 32 + idx];
            const ulonglong2* xr = (const ulonglong2*)(XL + k * 36) + seg * 2;
            ulonglong2 xa = xr[0], xb = xr[1];
            u64t ww = pk2(w, w);
            acc[0] = fma2(xa.x, ww, acc[0]);
            acc[1] = fma2(xa.y, ww, acc[1]);
            acc[2] = fma2(xb.x, ww, acc[2]);
            acc[3] = fma2(xb.y, ww, acc[3]);
        }
        int s = idx & 15;
        float* DST = (idx < 16) ? BS2 : CS2;
#pragma unroll
        for (int j = 0; j < 4; j++) {
            float lo, hi; upk2(acc[j], lo, hi);
            int t = seg * 8 + 2 * j;
            DST[t * 16 + s]       = lo;
            DST[(t + 1) * 16 + s] = hi;
        }
    }
    __syncthreads();

    // ---- phase 4: selective scan (ex2 on MUFU), gate folded ----
    {
        int i = tid >> 1;
        int hlf = tid & 1;
        float h[8], a2l[8];
#pragma unroll
        for (int u2 = 0; u2 < 8; u2++) { h[u2] = 0.f; a2l[u2] = A2S[hlf * 8 + u2]; }
        const float* dsrow = DS + i * 36;
        const float* xlrow = XL + i * 36;
        const float* garow = GA + i * 36;
        for (int t2 = 0; t2 < 16; t2++) {
            float2 dd = *(const float2*)(dsrow + 2 * t2);
            float2 xx = *(const float2*)(xlrow + 2 * t2);
            float2 gg = *(const float2*)(garow + 2 * t2);
#pragma unroll
            for (int sub = 0; sub < 2; sub++) {
                int t = 2 * t2 + sub;
                float d  = sub ? dd.y : dd.x;
                float xv = sub ? xx.y : xx.x;
                float dx = d * xv;
                const float4* bp = (const float4*)(BS2 + t * 16 + hlf * 8);
                const float4* cp = (const float4*)(CS2 + t * 16 + hlf * 8);
                float4 b0 = bp[0], b1 = bp[1];
                float4 c0v = cp[0], c1v = cp[1];
                float bb[8] = {b0.x, b0.y, b0.z, b0.w, b1.x, b1.y, b1.z, b1.w};
                float cc[8] = {c0v.x, c0v.y, c0v.z, c0v.w, c1v.x, c1v.y, c1v.z, c1v.w};
                float part = 0.f;
#pragma unroll
                for (int u2 = 0; u2 < 8; u2++) {
                    float e = ex2_fast(d * a2l[u2]);
                    h[u2] = fmaf(e, h[u2], dx * bb[u2]);
                    part = fmaf(h[u2], cc[u2], part);
                }
                part += __shfl_xor_sync(0xffffffffu, part, 1);
                if (hlf == 0) YS[i * 36 + t] = part * (sub ? gg.y : gg.x);
            }
        }
    }
    __syncthreads();

    // ---- phase 5: post-LN stats over di=128 per timestep (reduce ONLY) ----
    {
        int t = tid >> 3, g = tid & 7;
        float s1 = 0.f, s2 = 0.f;
#pragma unroll
        for (int m = 0; m < 16; m++) {
            float vv = YS[(g + m * 8) * 36 + t];
            s1 += vv; s2 += vv * vv;
        }
#pragma unroll
        for (int o = 4; o > 0; o >>= 1) {
            s1 += __shfl_down_sync(0xffffffffu, s1, o);
            s2 += __shfl_down_sync(0xffffffffu, s2, o);
        }
        if (g == 0) {
            float mu = s1 * (1.f / 128.f);
            float var = s2 * (1.f / 128.f) - mu * mu;
            MUSD[t] = mu;
            MUSD[32 + t] = rsqrtf(var + 1e-5f);
        }
    }
    __syncthreads();

    // ---- phase 6: out projection on RAW gated-y + LN-fold -> GA2 -> STG ----
    {
        int cp = tid & 31, jq = tid >> 5;
        int cc0 = 2 * cp;
        const float* wo = wT + WT_OUT;
        u64t oA[2], oB[2];
        oA[0] = oA[1] = oB[0] = oB[1] = 0ULL;
#pragma unroll 4
        for (int k = 0; k < 128; k++) {
            float2 w2 = ((const float2*)(wo + k * 64))[cp];
            ulonglong2 xv = *((const ulonglong2*)(YS + k * 36) + jq);
            u64t waa = pk2(w2.x, w2.x), wbb = pk2(w2.y, w2.y);
            oA[0] = fma2(xv.x, waa, oA[0]);
            oA[1] = fma2(xv.y, waa, oA[1]);
            oB[0] = fma2(xv.x, wbb, oB[0]);
            oB[1] = fma2(xv.y, wbb, oB[1]);
        }
        float S2a = wT[WT_S2 + cc0], S2b = wT[WT_S2 + cc0 + 1];
        float B2a = wT[WT_B2 + cc0], B2b = wT[WT_B2 + cc0 + 1];
        __syncthreads();
#pragma unroll
        for (int j = 0; j < 2; j++) {
            int t = jq * 4 + 2 * j;
            float2 mus = *(const float2*)(MUSD + t);
            float2 rss = *(const float2*)(MUSD + 32 + t);
            float tx = mus.x * rss.x, ty = mus.y * rss.y;
            u64t rr = pk2(rss.x, rss.y);
            u64t offA = pk2(fmaf(-tx, S2a, B2a), fmaf(-ty, S2a, B2a));
            u64t offB = pk2(fmaf(-tx, S2b, B2b), fmaf(-ty, S2b, B2b));
            u64t vA = fma2(oA[j], rr, offA);
            u64t vB = fma2(oB[j], rr, offB);
            float a0, a1; upk2(vA, a0, a1);
            GA2[t * 64 + cc0]       = a0;
            GA2[(t + 1) * 64 + cc0] = a1;
            upk2(vB, a0, a1);
            GA2[t * 64 + cc0 + 1]       = a0;
            GA2[(t + 1) * 64 + cc0 + 1] = a1;
        }
    }
    __syncthreads();
    for (int e = tid; e < 512; e += 256)
        ((float4*)oa)[e] = ((const float4*)GA2)[e];
}

// ---------------- final combine: identity + rs * softmax(axis_w) . outputs -----
__global__ void final_kernel(const float* __restrict__ x,
                             const float* __restrict__ o0, const float* __restrict__ o1,
                             const float* __restrict__ o2,
                             const float* __restrict__ rs, const float* __restrict__ axis_w,
                             float* __restrict__ out)
{
    __shared__ float S[2080];
    int blk = blockIdx.x, tid = threadIdx.x;
    int b = blk >> 10, h = (blk >> 5) & 31, w = blk & 31;
    float a0 = axis_w[0], a1 = axis_w[1], a2 = axis_w[2];
    float m = fmaxf(a0, fmaxf(a1, a2));
    float e0 = __expf(a0 - m), e1 = __expf(a1 - m), e2 = __expf(a2 - m);
    float r = rs[0] / (e0 + e1 + e2);
    float w0 = r * e0, w1 = r * e1, w2 = r * e2;
    long s2 = (long)blk * 2048;
    long s1 = ((long)(b * 1024 + h * 32)) * 2048 + w * 64;
    long s0 = ((long)(b * 1024 + w * 32)) * 2048 + h * 64;
    for (int e = tid; e < 2048; e += 256) {
        int d = e >> 6, c = e & 63;
        S[d * 65 + c] = w0 * o0[s0 + (long)d * 2048 + c]
                      + w1 * o1[s1 + (long)d * 2048 + c]
                      + w2 * o2[s2 + e];
    }
    __syncthreads();
    const float* xb = x + (size_t)b * 2097152 + h * 1024 + w * 32;
    float* ob = out + (size_t)b * 2097152 + h * 1024 + w * 32;
    for (int e = tid; e < 2048; e += 256) {
        int c = e >> 5, d = e & 31;
        ob[(size_t)c * 32768 + d] = xb[(size_t)c * 32768 + d] + S[d * 65 + c];
    }
}

// ---------------- launch ----------------
extern "C" void kernel_launch(void* const* d_in, const int* in_sizes, int n_in,
                              void* d_out, int out_size) {
    (void)in_sizes; (void)n_in; (void)out_size;
    const float* x        = (const float*)d_in[0];
    const float* cr1_w    = (const float*)d_in[1];
    const float* cr1_b    = (const float*)d_in[2];
    const float* cr2_w    = (const float*)d_in[3];
    const float* cr2_b    = (const float*)d_in[4];
    const float* ln_w     = (const float*)d_in[5];
    const float* ln_b     = (const float*)d_in[6];
    const float* left_w   = (const float*)d_in[7];
    const float* conv1d_w = (const float*)d_in[8];
    const float* conv1d_b = (const float*)d_in[9];
    const float* delta_w  = (const float*)d_in[10];
    const float* delta_b  = (const float*)d_in[11];
    const float* Bp_w     = (const float*)d_in[12];
    const float* Cp_w     = (const float*)d_in[13];
    const float* A_log    = (const float*)d_in[14];
    const float* right_w  = (const float*)d_in[15];
    const float* pn_w     = (const float*)d_in[16];
    const float* pn_b     = (const float*)d_in[17];
    const float* out_w    = (const float*)d_in[18];
    const float* res_scl  = (const float*)d_in[19];
    const float* axis_w   = (const float*)d_in[20];
    float* out = (float*)d_out;

    float *tmp, *x1, *xp0, *xp1, *xp2, *o0, *o1, *o2, *wT, *cwT;
    float2* ipart;
    cudaGetSymbolAddress((void**)&tmp, g_tmp);
    cudaGetSymbolAddress((void**)&x1, g_x1);
    cudaGetSymbolAddress((void**)&xp0, g_xp0);
    cudaGetSymbolAddress((void**)&xp1, g_xp1);
    cudaGetSymbolAddress((void**)&xp2, g_xp2);
    cudaGetSymbolAddress((void**)&o0, g_o0);
    cudaGetSymbolAddress((void**)&o1, g_o1);
    cudaGetSymbolAddress((void**)&o2, g_o2);
    cudaGetSymbolAddress((void**)&wT, g_wT);
    cudaGetSymbolAddress((void**)&cwT, g_cwT);
    cudaGetSymbolAddress((void**)&ipart, g_ipart);

    cudaFuncSetAttribute(conv3d_kernel, cudaFuncAttributeMaxDynamicSharedMemorySize,
                         CONV_SMEM_BYTES);
    cudaFuncSetAttribute(mamba_kernel, cudaFuncAttributeMaxDynamicSharedMemorySize,
                         MB_SMEM_FLOATS * (int)sizeof(float));

    // 1: conv weight transpose
    cwT_kernel<<<(221184 + 255) / 256, 256>>>(cr1_w, cr2_w, cwT);

    dim3 cg(32, 4, 2);
    // 2: conv1
    conv3d_kernel<<<cg, 256, CONV_SMEM_BYTES>>>(x, cwT, cr1_b, tmp);
    // 3: inorm1 (full: x1 = x + lrelu(norm(tmp)))
    inorm_res_kernel<<<128, 1024>>>(tmp, x, x1);
    // 4: conv2  (ncu capture slot)
    conv3d_kernel<<<cg, 256, CONV_SMEM_BYTES>>>(x1, cwT + 110592, cr2_b, tmp);
    // 5: inorm2 stats only
    inorm_stats_kernel<<<128, 1024>>>(tmp, ipart);
    // 6: trans (x2 inline + per-voxel LN stats + fold constants)
    trans_kernel<<<2048 + 177, 256>>>(tmp, x1, ipart, left_w, right_w, delta_w, out_w,
                                      Bp_w, Cp_w, pn_w, pn_b, xp0, xp1, xp2, wT);
    // 7: mamba
    mamba_kernel<<<dim3(2048, 3), 256, MB_SMEM_FLOATS * (int)sizeof(float)>>>(
        xp0, xp1, xp2, ln_w, ln_b, conv1d_w, conv1d_b, delta_b, A_log,
        wT, o0, o1, o2);
    // 8: final
    final_kernel<<<2048, 256>>>(x, o0, o1, o2, res_scl, axis_w, out);
}